// round 4
// baseline (speedup 1.0000x reference)
#include <cuda_runtime.h>

#define BB 4
#define LL 1024
#define VV 1280
#define NE 768
#define NB 8
#define NH 32
#define NO 256          // NB*NH
#define NC 32           // chunks over L
#define CH 32           // chunk size (NC*CH == LL)

// Scratch (device globals: no allocation allowed)
__device__ float g_x[BB * LL * NO];          // 4 MB  : x = h @ W1
__device__ int   g_chunk_first[BB * NC * VV]; // 640 KB: first occurrence of v within chunk
__device__ int   g_next[BB * NC * VV];        // 640 KB: first occurrence of v in chunks > c

// ---------------------------------------------------------------------------
// GEMM1: x[4096,256] = h[4096,768] @ W1[768,256]
// 64x64 block tile, BK=16, 256 threads, 4x4 register tile per thread.
// ---------------------------------------------------------------------------
__global__ __launch_bounds__(256) void gemm1_kernel(
    const float* __restrict__ h, const float* __restrict__ W1)
{
    __shared__ float As[16][64];   // transposed: As[k][m]
    __shared__ float Bs[16][64];   // Bs[k][n]

    const int tid = threadIdx.x;
    const int tx = tid & 15;
    const int ty = tid >> 4;
    const int m0 = blockIdx.y * 64;
    const int n0 = blockIdx.x * 64;

    const int ar = tid >> 2;         // 0..63  (m within tile)
    const int ac = (tid & 3) * 4;    // 0,4,8,12 (k within tile)
    const int br = tid >> 4;         // 0..15  (k within tile)
    const int bc = (tid & 15) * 4;   // 0..60  (n within tile)

    float acc[4][4];
#pragma unroll
    for (int i = 0; i < 4; ++i)
#pragma unroll
        for (int j = 0; j < 4; ++j) acc[i][j] = 0.0f;

    for (int k0 = 0; k0 < NE; k0 += 16) {
        float4 av = *(const float4*)&h[(m0 + ar) * NE + k0 + ac];
        float4 bv = *(const float4*)&W1[(k0 + br) * NO + n0 + bc];
        As[ac + 0][ar] = av.x;
        As[ac + 1][ar] = av.y;
        As[ac + 2][ar] = av.z;
        As[ac + 3][ar] = av.w;
        *(float4*)&Bs[br][bc] = bv;
        __syncthreads();

#pragma unroll
        for (int kk = 0; kk < 16; ++kk) {
            float4 a4 = *(const float4*)&As[kk][ty * 4];
            float4 b4 = *(const float4*)&Bs[kk][tx * 4];
            float a_[4] = {a4.x, a4.y, a4.z, a4.w};
            float b_[4] = {b4.x, b4.y, b4.z, b4.w};
#pragma unroll
            for (int i = 0; i < 4; ++i)
#pragma unroll
                for (int j = 0; j < 4; ++j)
                    acc[i][j] += a_[i] * b_[j];
        }
        __syncthreads();
    }

#pragma unroll
    for (int i = 0; i < 4; ++i) {
        *(float4*)&g_x[(m0 + ty * 4 + i) * NO + n0 + tx * 4] =
            make_float4(acc[i][0], acc[i][1], acc[i][2], acc[i][3]);
    }
}

// ---------------------------------------------------------------------------
// GEMM2: logits[m][n][v] = sum_h x[m][n*32+h] * W2[h][v]
// Block: 8 m-rows x 128 v-cols x all 8 bins. 256 threads.
// Thread: (mh = tid>>7 selects 4 m-rows) x 8 bins x 1 v.
// ---------------------------------------------------------------------------
__global__ __launch_bounds__(256) void gemm2_kernel(
    const float* __restrict__ W2, float* __restrict__ logits)
{
    __shared__ float W2s[32][128];  // 16 KB
    __shared__ float xs[8][256];    // 8 KB

    const int tid = threadIdx.x;
    const int v0 = blockIdx.x * 128;
    const int m0 = blockIdx.y * 8;

#pragma unroll
    for (int it = 0; it < 16; ++it) {
        int idx = tid + it * 256;           // 0..4095
        W2s[idx >> 7][idx & 127] = W2[(idx >> 7) * VV + v0 + (idx & 127)];
    }
#pragma unroll
    for (int it = 0; it < 2; ++it) {
        int f4 = tid + it * 256;            // 0..511 float4s
        int r = f4 >> 6;                    // 0..7
        int cc = (f4 & 63) << 2;            // 0..252
        *(float4*)&xs[r][cc] = *(const float4*)&g_x[(m0 + r) * NO + cc];
    }
    __syncthreads();

    const int vloc = tid & 127;
    const int mh = tid >> 7;                // 0 or 1

    float acc[4][8];
#pragma unroll
    for (int mi = 0; mi < 4; ++mi)
#pragma unroll
        for (int n = 0; n < 8; ++n) acc[mi][n] = 0.0f;

#pragma unroll
    for (int h4 = 0; h4 < 8; ++h4) {
        const int hh = h4 * 4;
        float w0 = W2s[hh + 0][vloc];
        float w1 = W2s[hh + 1][vloc];
        float w2 = W2s[hh + 2][vloc];
        float w3 = W2s[hh + 3][vloc];
#pragma unroll
        for (int n = 0; n < 8; ++n) {
#pragma unroll
            for (int mi = 0; mi < 4; ++mi) {
                float4 a = *(const float4*)&xs[mh * 4 + mi][n * 32 + hh];
                acc[mi][n] += a.x * w0;
                acc[mi][n] += a.y * w1;
                acc[mi][n] += a.z * w2;
                acc[mi][n] += a.w * w3;
            }
        }
    }

#pragma unroll
    for (int mi = 0; mi < 4; ++mi) {
        const int m = m0 + mh * 4 + mi;
#pragma unroll
        for (int n = 0; n < 8; ++n) {
            logits[(m * NB + n) * VV + v0 + vloc] = acc[mi][n];
        }
    }
}

// ---------------------------------------------------------------------------
// Kernel A: per-chunk first occurrence. Block per (b, c); smem atomicMin.
// ---------------------------------------------------------------------------
__global__ __launch_bounds__(256) void first_occ_kernel(const int* __restrict__ targets)
{
    __shared__ int arr[VV];
    const int b = blockIdx.x >> 5;
    const int c = blockIdx.x & 31;
    const int tid = threadIdx.x;

#pragma unroll
    for (int it = 0; it < 5; ++it) arr[tid + it * 256] = LL;
    __syncthreads();
    if (tid < CH) {
        int j = c * CH + tid;
        atomicMin(&arr[targets[b * LL + j]], j);
    }
    __syncthreads();
#pragma unroll
    for (int it = 0; it < 5; ++it) {
        int idx = tid + it * 256;
        g_chunk_first[(b * NC + c) * VV + idx] = arr[idx];
    }
}

// ---------------------------------------------------------------------------
// Kernel B: exclusive suffix-min over chunks. One thread per (b, v).
// g_next[b][c][v] = min over c' > c of g_chunk_first[b][c'][v], else LL.
// ---------------------------------------------------------------------------
__global__ __launch_bounds__(256) void suffix_kernel()
{
    const int gt = blockIdx.x * 256 + threadIdx.x;   // 0..5119
    const int b = gt / VV;
    const int v = gt - b * VV;

    int cf[NC];
#pragma unroll
    for (int c = 0; c < NC; ++c) cf[c] = g_chunk_first[(b * NC + c) * VV + v];

    int run = LL;
#pragma unroll
    for (int c = NC - 1; c >= 0; --c) {
        g_next[(b * NC + c) * VV + v] = run;
        run = min(run, cf[c]);
    }
}

// ---------------------------------------------------------------------------
// Kernel C: tte + censor mask. Block per (b, c), 320 threads, 4 v per thread.
// Backward scan within chunk; writes tte (float4) + 8 mask planes (float4).
// ---------------------------------------------------------------------------
__global__ __launch_bounds__(320) void tte_mask_kernel(
    const int* __restrict__ targets,
    const float* __restrict__ age,
    const float* __restrict__ targets_age,
    float* __restrict__ out_tte,
    float* __restrict__ out_mask)
{
    __shared__ float ta_s[LL];
    __shared__ int ts[CH];
    __shared__ float ag[CH];

    const int b = blockIdx.x >> 5;
    const int c = blockIdx.x & 31;
    const int tid = threadIdx.x;        // 0..319

    for (int idx = tid; idx < LL; idx += 320)
        ta_s[idx] = targets_age[b * LL + idx];
    if (tid < CH) {
        int i = c * CH + tid;
        ts[tid] = targets[b * LL + i];
        ag[tid] = age[b * LL + i];
    }
    __syncthreads();

    const int vb = tid * 4;             // 0..1276
    int4 c4 = *(const int4*)&g_next[(b * NC + c) * VV + vb];
    int cur0 = c4.x, cur1 = c4.y, cur2 = c4.z, cur3 = c4.w;

    for (int jj = CH - 1; jj >= 0; --jj) {
        const int i = c * CH + jj;
        const int t = ts[jj];
        const float ai = ag[jj];

        if (t == vb + 0) cur0 = i;
        if (t == vb + 1) cur1 = i;
        if (t == vb + 2) cur2 = i;
        if (t == vb + 3) cur3 = i;

        float tte[4];
        bool nev[4];
        int curs[4] = {cur0, cur1, cur2, cur3};
#pragma unroll
        for (int q = 0; q < 4; ++q) {
            int vv = vb + q;
            int idxr = curs[q];
            if (vv == 0 && i > 0) idxr = 0;  // reference's where(upper, targets, 0) quirk
            bool ne = (idxr == LL);
            int idx = ne ? (LL - 1) : idxr;
            tte[q] = ta_s[idx] - ai;
            nev[q] = ne;
        }

        const int row = b * LL + i;
        *(float4*)&out_tte[row * VV + vb] = make_float4(tte[0], tte[1], tte[2], tte[3]);

        // bin index via exact edge comparisons (edges k*1.25 exact in fp32)
        int bin[4];
        bool valid[4];
#pragma unroll
        for (int q = 0; q < 4; ++q) {
            float tq = tte[q];
            valid[q] = (tq >= 0.0f) && (tq < 10.0f);
            bin[q] = (tq >= 1.25f) + (tq >= 2.5f) + (tq >= 3.75f) + (tq >= 5.0f)
                   + (tq >= 6.25f) + (tq >= 7.5f) + (tq >= 8.75f);
        }

        const int mbase = row * NB * VV + vb;
#pragma unroll
        for (int n = 0; n < 8; ++n) {
            float4 mv;
            mv.x = (nev[0] || (valid[0] && bin[0] == n)) ? 1.0f : 0.0f;
            mv.y = (nev[1] || (valid[1] && bin[1] == n)) ? 1.0f : 0.0f;
            mv.z = (nev[2] || (valid[2] && bin[2] == n)) ? 1.0f : 0.0f;
            mv.w = (nev[3] || (valid[3] && bin[3] == n)) ? 1.0f : 0.0f;
            *(float4*)&out_mask[mbase + n * VV] = mv;
        }
    }
}

// ---------------------------------------------------------------------------
extern "C" void kernel_launch(void* const* d_in, const int* in_sizes, int n_in,
                              void* d_out, int out_size)
{
    const float* h   = (const float*)d_in[0];  // (B,L,768) f32
    const float* age = (const float*)d_in[1];  // (B,L) f32
    const float* ta  = (const float*)d_in[2];  // (B,L) f32 targets_age
    // d_in[3] = delta_t (unused by outputs)
    const int*   tg  = (const int*)d_in[4];    // (B,L) i32 targets
    const float* W1  = (const float*)d_in[5];  // (768,256) f32
    const float* W2  = (const float*)d_in[6];  // (32,1280) f32

    float* out = (float*)d_out;
    float* out_logits = out;                                  // B*L*8*V
    float* out_tte    = out + (size_t)BB * LL * NB * VV;      // B*L*V
    float* out_mask   = out_tte + (size_t)BB * LL * VV;       // B*L*8*V

    gemm1_kernel<<<dim3(NO / 64, (BB * LL) / 64), 256>>>(h, W1);
    gemm2_kernel<<<dim3(VV / 128, (BB * LL) / 8), 256>>>(W2, out_logits);
    first_occ_kernel<<<BB * NC, 256>>>(tg);
    suffix_kernel<<<(BB * VV) / 256, 256>>>();
    tte_mask_kernel<<<BB * NC, 320>>>(tg, age, ta, out_tte, out_mask);
}